// round 15
// baseline (speedup 1.0000x reference)
#include <cuda_runtime.h>
#include <cuda_fp16.h>
#include <cstdint>
#include <cstddef>

#define NN   65536
#define F    512
#define KNN  16
#define NOUT 1024

#define BM 128
#define BN 64
#define BK 64
#define STAGES 2
#define GEMM_THREADS 128           // 4 warps: 2 (m) x 2 (n), warp tile 64x32
#define NKTILES (F / BK)           // 8
#define GEMM_BLOCKS 4096           // (NN/BM) * (512/BN) per GEMM half

// smem row: 64 fp16 data + 8 pad = 72 elems = 144B
#define ROWB 144
#define A_TILE_BYTES (BM * ROWB)                    // 18432
#define B_TILE_BYTES (BN * ROWB)                    // 9216
#define STAGE_BYTES  (A_TILE_BYTES + B_TILE_BYTES)  // 27648
#define SM_TOTAL (STAGES * STAGE_BYTES)             // 55296 (x4 CTAs = 221KB/SM)

// prep: A = 4096 blocks x 256 thr x 8 f4 (MLP=8); W = 512 x 256 x 4
#define PREP_A_BLOCKS 4096
#define PREP_W_BLOCKS 512
#define PREP_BLOCKS   (PREP_A_BLOCKS + PREP_W_BLOCKS + 1)

// mixed kernel: every 9th block is a hdst-GEMM block; rest gather
#define MIX_BLOCKS (9 * GEMM_BLOCKS)     // 36864 = 4096 gemm + 32768 gather

// ---------------- scratch (__device__ globals) ------------------------------
__device__ __align__(1024) __half  g_hdst16[(size_t)NN * F];   // 64MB (phi-theta)
__device__ __align__(1024) __half  g_theta16[(size_t)NN * F];  // 64MB
__device__ __align__(1024) __half  g_max16[(size_t)NN * F];    // 64MB
__device__ __align__(1024) __half  g_A16[(size_t)NN * F];      // 64MB
__device__ __align__(1024) __half  g_BT16[(size_t)NOUT * F];   // 1MB
__device__ int g_idx_is64;

// ---------------- helpers ----------------------------------------------------
__device__ __forceinline__ uint32_t smem_to_u32(const void* p) {
    uint32_t a;
    asm("{ .reg .u64 t; cvta.to.shared.u64 t, %1; cvt.u32.u64 %0, t; }"
        : "=r"(a) : "l"(p));
    return a;
}
__device__ __forceinline__ void cp16(uint32_t dst, const void* src) {
    asm volatile("cp.async.cg.shared.global [%0], [%1], 16;" :: "r"(dst), "l"(src));
}
__device__ __forceinline__ void ldmatrix_x4(uint32_t* r, uint32_t addr) {
    asm volatile("ldmatrix.sync.aligned.m8n8.x4.shared.b16 {%0,%1,%2,%3}, [%4];"
                 : "=r"(r[0]), "=r"(r[1]), "=r"(r[2]), "=r"(r[3]) : "r"(addr));
}
__device__ __forceinline__ void mma_f16(float* c, const uint32_t* a, const uint32_t* b) {
    asm volatile(
        "mma.sync.aligned.m16n8k16.row.col.f32.f16.f16.f32 "
        "{%0,%1,%2,%3}, {%4,%5,%6,%7}, {%8,%9}, {%0,%1,%2,%3};"
        : "+f"(c[0]), "+f"(c[1]), "+f"(c[2]), "+f"(c[3])
        : "r"(a[0]), "r"(a[1]), "r"(a[2]), "r"(a[3]), "r"(b[0]), "r"(b[1]));
}

// ---------------- fused prep: detect + convert_A + convert_W -----------------
__global__ __launch_bounds__(256) void prep_kernel(
    const float* __restrict__ A,
    const float* __restrict__ Wt,
    const float* __restrict__ Wp,
    const unsigned int* __restrict__ srcw)
{
    const int b = blockIdx.x;
    if (b < PREP_A_BLOCKS) {
        const size_t stride = (size_t)PREP_A_BLOCKS * 256;
        const size_t base = (size_t)b * 256 + threadIdx.x;
        float4 v[8];
#pragma unroll
        for (int u = 0; u < 8; u++)
            v[u] = reinterpret_cast<const float4*>(A)[base + u * stride];
#pragma unroll
        for (int u = 0; u < 8; u++) {
            __half2 h0 = __floats2half2_rn(v[u].x, v[u].y);
            __half2 h1 = __floats2half2_rn(v[u].z, v[u].w);
            uint2 packed;
            packed.x = *reinterpret_cast<uint32_t*>(&h0);
            packed.y = *reinterpret_cast<uint32_t*>(&h1);
            reinterpret_cast<uint2*>(g_A16)[base + u * stride] = packed;
        }
    } else if (b < PREP_A_BLOCKS + PREP_W_BLOCKS) {
        const int base = (b - PREP_A_BLOCKS) * 256 + threadIdx.x;
        const int stride = PREP_W_BLOCKS * 256;
#pragma unroll
        for (int u = 0; u < 4; u++) {
            const int idx = base + u * stride;      // [0, 1024*512)
            const int n = idx >> 9;
            const int k = idx & 511;
            const int nc = n & 511;
            float w;
            if (n < 512) w = Wt[(size_t)k * 512 + nc];
            else         w = Wp[(size_t)k * 512 + nc] - Wt[(size_t)k * 512 + nc];
            g_BT16[(size_t)n * F + k] = __float2half_rn(w);
        }
    } else if (threadIdx.x < 32) {
        const int lane = threadIdx.x;
        int bad = 0;
        for (int i = 1 + 2 * lane; i < 512; i += 64)
            if (srcw[i] != 0u) bad = 1;
        const int any_bad = __any_sync(0xFFFFFFFFu, bad);
        if (lane == 0) g_idx_is64 = any_bad ? 0 : 1;
    }
}

// ---------------- GEMM body (one 512-col half) --------------------------------
// gid in [0, GEMM_BLOCKS); n_base = 0 (theta) or 512 (hdst).
__device__ __forceinline__ void load_tile(uint32_t sm_base, int stage, int t,
                                          int m0, int n0, int tid) {
    const int kc = t * BK;
    const uint32_t smA = sm_base + stage * STAGE_BYTES;
    const uint32_t smB = smA + A_TILE_BYTES;
#pragma unroll
    for (int i = 0; i < 8; i++) {
        const int q = tid + i * GEMM_THREADS;
        const int r = q >> 3;
        const int c = q & 7;
        cp16(smA + r * ROWB + c * 16,
             g_A16 + (size_t)(m0 + r) * F + kc + c * 8);
    }
#pragma unroll
    for (int i = 0; i < 4; i++) {
        const int q = tid + i * GEMM_THREADS;
        const int r = q >> 3;
        const int c = q & 7;
        cp16(smB + r * ROWB + c * 16,
             g_BT16 + (size_t)(n0 + r) * F + kc + c * 8);
    }
    asm volatile("cp.async.commit_group;" ::: "memory");
}

__device__ __forceinline__ void gemm_body(uint32_t sm_base, int gid, int n_base,
                                          __half* __restrict__ outbase)
{
    const int tid = threadIdx.x;
    const int wid = tid >> 5;
    const int lid = tid & 31;

    // swizzle: groups of 32 m-blocks sweep all 8 n-blocks of this half
    const int group = gid >> 8;
    const int inner = gid & 255;
    const int n_blk = inner >> 5;
    const int m_blk = (group << 5) | (inner & 31);
    const int m0 = m_blk * BM;
    const int n0 = n_base + n_blk * BN;       // global B^T row
    const int nc0 = n_blk * BN;               // column within output half

    const int wm0 = (wid >> 1) * 64;
    const int wn0 = (wid & 1) * 32;

    float acc[4][4][4];
#pragma unroll
    for (int i = 0; i < 4; i++)
#pragma unroll
        for (int j = 0; j < 4; j++)
#pragma unroll
            for (int q = 0; q < 4; q++) acc[i][j][q] = 0.f;

    load_tile(sm_base, 0, 0, m0, n0, tid);
    load_tile(sm_base, 1, 1, m0, n0, tid);

    const int a_row_off = wm0 + (lid & 15);
    const int a_col_off = (lid >> 4) * 8;
    const int b_row_off = wn0 + ((lid & 16) >> 1) + (lid & 7);
    const int b_col_off = ((lid & 8) ? 8 : 0);

    for (int t = 0; t < NKTILES; t++) {
        const int st = t & 1;
        if (t + 1 < NKTILES) asm volatile("cp.async.wait_group 1;" ::: "memory");
        else                 asm volatile("cp.async.wait_group 0;" ::: "memory");
        __syncthreads();

        const uint32_t smA = sm_base + st * STAGE_BYTES;
        const uint32_t smB = smA + A_TILE_BYTES;

#pragma unroll
        for (int ks = 0; ks < 4; ks++) {
            const int col = ks * 16;
            uint32_t a[4][4], b[4][2];
#pragma unroll
            for (int i = 0; i < 4; i++)
                ldmatrix_x4(a[i], smA + (a_row_off + i * 16) * ROWB
                                      + (col + a_col_off) * 2);
#pragma unroll
            for (int j2 = 0; j2 < 2; j2++) {
                uint32_t r[4];
                ldmatrix_x4(r, smB + (b_row_off + j2 * 16) * ROWB
                                   + (col + b_col_off) * 2);
                b[j2 * 2 + 0][0] = r[0]; b[j2 * 2 + 0][1] = r[1];
                b[j2 * 2 + 1][0] = r[2]; b[j2 * 2 + 1][1] = r[3];
            }
#pragma unroll
            for (int i = 0; i < 4; i++)
#pragma unroll
                for (int j = 0; j < 4; j++)
                    mma_f16(acc[i][j], a[i], b[j]);
        }

        __syncthreads();
        if (t + 2 < NKTILES)
            load_tile(sm_base, st, t + 2, m0, n0, tid);
    }

    const int er = lid >> 2;
    const int ec = (lid & 3) * 2;
#pragma unroll
    for (int i = 0; i < 4; i++) {
#pragma unroll
        for (int j = 0; j < 4; j++) {
            const int m = m0 + wm0 + i * 16 + er;
            const int n = nc0 + wn0 + j * 8 + ec;
            *reinterpret_cast<__half2*>(&outbase[(size_t)m * F + n]) =
                __float22half2_rn(make_float2(acc[i][j][0], acc[i][j][1]));
            *reinterpret_cast<__half2*>(&outbase[(size_t)(m + 8) * F + n]) =
                __float22half2_rn(make_float2(acc[i][j][2], acc[i][j][3]));
        }
    }
}

// ---------------- theta GEMM ---------------------------------------------------
__global__ __launch_bounds__(GEMM_THREADS, 4) void theta_gemm_kernel() {
    extern __shared__ __align__(128) char smem[];
    gemm_body(smem_to_u32(smem), blockIdx.x, 0, g_theta16);
}

// ---------------- gather-max body (writes fp16 max) ---------------------------
__device__ __forceinline__ void gather_body(int gidx, const void* __restrict__ src)
{
    const int grp  = threadIdx.x >> 6;               // 0..1 : node within block
    const int lane = threadIdx.x & 63;               // 0..63: uint4 lane
    const int n    = gidx * 2 + grp;

    __shared__ unsigned int sidx[2][KNN];
    if (lane < KNN) {
        if (g_idx_is64) {
            sidx[grp][lane] = (unsigned int)((const unsigned long long*)src)
                                  [(size_t)n * KNN + lane] & 0xFFFFu;
        } else {
            sidx[grp][lane] = ((const unsigned int*)src)
                                  [(size_t)n * KNN + lane] & 0xFFFFu;
        }
    }
    __syncthreads();

    const uint4* __restrict__ t16 = reinterpret_cast<const uint4*>(g_theta16);

    uint4 raw = t16[(size_t)sidx[grp][0] * (F / 8) + lane];
    __half2 m0 = *reinterpret_cast<__half2*>(&raw.x);
    __half2 m1 = *reinterpret_cast<__half2*>(&raw.y);
    __half2 m2 = *reinterpret_cast<__half2*>(&raw.z);
    __half2 m3 = *reinterpret_cast<__half2*>(&raw.w);
#pragma unroll
    for (int j = 1; j < KNN; j++) {
        uint4 r = t16[(size_t)sidx[grp][j] * (F / 8) + lane];
        m0 = __hmax2(m0, *reinterpret_cast<__half2*>(&r.x));
        m1 = __hmax2(m1, *reinterpret_cast<__half2*>(&r.y));
        m2 = __hmax2(m2, *reinterpret_cast<__half2*>(&r.z));
        m3 = __hmax2(m3, *reinterpret_cast<__half2*>(&r.w));
    }

    uint4 o;
    o.x = *reinterpret_cast<uint32_t*>(&m0);
    o.y = *reinterpret_cast<uint32_t*>(&m1);
    o.z = *reinterpret_cast<uint32_t*>(&m2);
    o.w = *reinterpret_cast<uint32_t*>(&m3);
    reinterpret_cast<uint4*>(g_max16)[(size_t)n * (F / 8) + lane] = o;
}

// ---------------- mixed: hdst GEMM + gather-max interleaved -------------------
// bid % 9 == 0 -> hdst GEMM block (bid/9); else gather block.
__global__ __launch_bounds__(GEMM_THREADS, 4) void mixed_kernel(
    const void* __restrict__ src)
{
    extern __shared__ __align__(128) char smem[];
    const int bid = blockIdx.x;
    const int q = bid / 9;
    const int r = bid - q * 9;
    if (r == 0) {
        gemm_body(smem_to_u32(smem), q, 512, g_hdst16);
    } else {
        gather_body(q * 8 + (r - 1), src);
    }
}

// ---------------- add: out = max16 + hdst16 ------------------------------------
// 4096 blocks x 256 thr x 4 uint4 (8 halves each), MLP=4
#define ADD_BLOCKS 4096
__global__ __launch_bounds__(256) void add_kernel(float* __restrict__ out) {
    const size_t stride = (size_t)ADD_BLOCKS * 256;
    const size_t base = (size_t)blockIdx.x * 256 + threadIdx.x;
    uint4 mv[4], hv[4];
#pragma unroll
    for (int u = 0; u < 4; u++) {
        mv[u] = reinterpret_cast<const uint4*>(g_max16)[base + u * stride];
        hv[u] = reinterpret_cast<const uint4*>(g_hdst16)[base + u * stride];
    }
#pragma unroll
    for (int u = 0; u < 4; u++) {
        const __half2* mp = reinterpret_cast<const __half2*>(&mv[u]);
        const __half2* hp = reinterpret_cast<const __half2*>(&hv[u]);
        float4 r0, r1;
        float2 a0 = __half22float2(mp[0]), b0 = __half22float2(hp[0]);
        float2 a1 = __half22float2(mp[1]), b1 = __half22float2(hp[1]);
        float2 a2 = __half22float2(mp[2]), b2 = __half22float2(hp[2]);
        float2 a3 = __half22float2(mp[3]), b3 = __half22float2(hp[3]);
        r0.x = a0.x + b0.x; r0.y = a0.y + b0.y;
        r0.z = a1.x + b1.x; r0.w = a1.y + b1.y;
        r1.x = a2.x + b2.x; r1.y = a2.y + b2.y;
        r1.z = a3.x + b3.x; r1.w = a3.y + b3.y;
        reinterpret_cast<float4*>(out)[(base + u * stride) * 2 + 0] = r0;
        reinterpret_cast<float4*>(out)[(base + u * stride) * 2 + 1] = r1;
    }
}

// ---------------------------------------------------------------------------------
extern "C" void kernel_launch(void* const* d_in, const int* in_sizes, int n_in,
                              void* d_out, int out_size)
{
    const void*  src  = nullptr;
    const float* feat = nullptr;
    const float* Wt   = nullptr;
    const float* Wp   = nullptr;

    for (int i = 0; i < n_in; i++) {
        const int s = in_sizes[i];
        if (s == NN * KNN)      src  = d_in[i];
        else if (s == NN * F)   feat = (const float*)d_in[i];
        else if (s == F * F) {
            if (!Wt) Wt = (const float*)d_in[i];
            else     Wp = (const float*)d_in[i];
        }
    }

    cudaFuncSetAttribute(theta_gemm_kernel,
                         cudaFuncAttributeMaxDynamicSharedMemorySize, SM_TOTAL);
    cudaFuncSetAttribute(mixed_kernel,
                         cudaFuncAttributeMaxDynamicSharedMemorySize, SM_TOTAL);

    prep_kernel<<<PREP_BLOCKS, 256>>>(feat, Wt, Wp, (const unsigned int*)src);
    theta_gemm_kernel<<<GEMM_BLOCKS, GEMM_THREADS, SM_TOTAL>>>();
    mixed_kernel<<<MIX_BLOCKS, GEMM_THREADS, SM_TOTAL>>>(src);
    add_kernel<<<ADD_BLOCKS, 256>>>((float*)d_out);
}

// round 16
// speedup vs baseline: 1.3560x; 1.3560x over previous
#include <cuda_runtime.h>
#include <cuda_fp16.h>
#include <cstdint>
#include <cstddef>

#define NN   65536
#define F    512
#define KNN  16
#define NOUT 1024

#define BM 128
#define BN 64
#define BK 64
#define STAGES 2
#define GEMM_THREADS 128           // 4 warps: 2 (m) x 2 (n), warp tile 64x32
#define NKTILES (F / BK)           // 8

// smem row: 64 fp16 data + 8 pad = 72 elems = 144B
#define ROWB 144
#define A_TILE_BYTES (BM * ROWB)                    // 18432
#define B_TILE_BYTES (BN * ROWB)                    // 9216
#define STAGE_BYTES  (A_TILE_BYTES + B_TILE_BYTES)  // 27648
#define SM_TOTAL (STAGES * STAGE_BYTES)             // 55296 (x4 CTAs = 221KB/SM)

// prep: A = 4096 blocks x 256 thr x 8 float4 (MLP=8); W = 512 x 256 x 4
#define PREP_A_BLOCKS 4096
#define PREP_W_BLOCKS 512
#define PREP_BLOCKS   (PREP_A_BLOCKS + PREP_W_BLOCKS + 1)

// ---------------- scratch (__device__ globals) ------------------------------
__device__ __align__(1024) __half  g_hdst16[(size_t)NN * F];   // 64MB (phi-theta)
__device__ __align__(1024) __half  g_theta16[(size_t)NN * F];  // 64MB
__device__ __align__(1024) __half  g_A16[(size_t)NN * F];      // 64MB
__device__ __align__(1024) __half  g_BT16[(size_t)NOUT * F];   // 1MB
__device__ int g_idx_is64;

// ---------------- helpers ----------------------------------------------------
__device__ __forceinline__ uint32_t smem_to_u32(const void* p) {
    uint32_t a;
    asm("{ .reg .u64 t; cvta.to.shared.u64 t, %1; cvt.u32.u64 %0, t; }"
        : "=r"(a) : "l"(p));
    return a;
}
__device__ __forceinline__ void cp16(uint32_t dst, const void* src) {
    asm volatile("cp.async.cg.shared.global [%0], [%1], 16;" :: "r"(dst), "l"(src));
}
__device__ __forceinline__ void ldmatrix_x4(uint32_t* r, uint32_t addr) {
    asm volatile("ldmatrix.sync.aligned.m8n8.x4.shared.b16 {%0,%1,%2,%3}, [%4];"
                 : "=r"(r[0]), "=r"(r[1]), "=r"(r[2]), "=r"(r[3]) : "r"(addr));
}
__device__ __forceinline__ void mma_f16(float* c, const uint32_t* a, const uint32_t* b) {
    asm volatile(
        "mma.sync.aligned.m16n8k16.row.col.f32.f16.f16.f32 "
        "{%0,%1,%2,%3}, {%4,%5,%6,%7}, {%8,%9}, {%0,%1,%2,%3};"
        : "+f"(c[0]), "+f"(c[1]), "+f"(c[2]), "+f"(c[3])
        : "r"(a[0]), "r"(a[1]), "r"(a[2]), "r"(a[3]), "r"(b[0]), "r"(b[1]));
}

// ---------------- fused prep: detect + convert_A + convert_W -----------------
__global__ __launch_bounds__(256) void prep_kernel(
    const float* __restrict__ A,
    const float* __restrict__ Wt,
    const float* __restrict__ Wp,
    const unsigned int* __restrict__ srcw)
{
    const int b = blockIdx.x;
    if (b < PREP_A_BLOCKS) {
        const size_t stride = (size_t)PREP_A_BLOCKS * 256;
        const size_t base = (size_t)b * 256 + threadIdx.x;
        float4 v[8];
#pragma unroll
        for (int u = 0; u < 8; u++)
            v[u] = reinterpret_cast<const float4*>(A)[base + u * stride];
#pragma unroll
        for (int u = 0; u < 8; u++) {
            __half2 h0 = __floats2half2_rn(v[u].x, v[u].y);
            __half2 h1 = __floats2half2_rn(v[u].z, v[u].w);
            uint2 packed;
            packed.x = *reinterpret_cast<uint32_t*>(&h0);
            packed.y = *reinterpret_cast<uint32_t*>(&h1);
            reinterpret_cast<uint2*>(g_A16)[base + u * stride] = packed;
        }
    } else if (b < PREP_A_BLOCKS + PREP_W_BLOCKS) {
        // W -> B^T fp16: rows [0,512)=Wt^T, [512,1024)=(Wp-Wt)^T
        const int base = (b - PREP_A_BLOCKS) * 256 + threadIdx.x;
        const int stride = PREP_W_BLOCKS * 256;
#pragma unroll
        for (int u = 0; u < 4; u++) {
            const int idx = base + u * stride;      // [0, 1024*512)
            const int n = idx >> 9;
            const int k = idx & 511;
            const int nc = n & 511;
            float w;
            if (n < 512) w = Wt[(size_t)k * 512 + nc];
            else         w = Wp[(size_t)k * 512 + nc] - Wt[(size_t)k * 512 + nc];
            g_BT16[(size_t)n * F + k] = __float2half_rn(w);
        }
    } else if (threadIdx.x < 32) {
        // index width detection (int64 with values < 2^16 -> odd words all 0)
        const int lane = threadIdx.x;
        int bad = 0;
        for (int i = 1 + 2 * lane; i < 512; i += 64)
            if (srcw[i] != 0u) bad = 1;
        const int any_bad = __any_sync(0xFFFFFFFFu, bad);
        if (lane == 0) g_idx_is64 = any_bad ? 0 : 1;
    }
}

// ---------------- HMMA dual GEMM ----------------------------------------------
// C[65536 x 1024] = A16 @ [Wt | Wp-Wt], fp16 in, fp32 acc.
// CTA tile 128x64, 4 warps (2m x 2n), warp tile 64x32, 2 stages, 4 CTAs/SM.
__device__ __forceinline__ void load_tile(uint32_t sm_base, int stage, int t,
                                          int m0, int n0, int tid) {
    const int kc = t * BK;
    const uint32_t smA = sm_base + stage * STAGE_BYTES;
    const uint32_t smB = smA + A_TILE_BYTES;
#pragma unroll
    for (int i = 0; i < 8; i++) {               // A: 128 rows x 8 chunks = 1024
        const int q = tid + i * GEMM_THREADS;
        const int r = q >> 3;
        const int c = q & 7;
        cp16(smA + r * ROWB + c * 16,
             g_A16 + (size_t)(m0 + r) * F + kc + c * 8);
    }
#pragma unroll
    for (int i = 0; i < 4; i++) {               // B: 64 rows x 8 chunks = 512
        const int q = tid + i * GEMM_THREADS;
        const int r = q >> 3;
        const int c = q & 7;
        cp16(smB + r * ROWB + c * 16,
             g_BT16 + (size_t)(n0 + r) * F + kc + c * 8);
    }
    asm volatile("cp.async.commit_group;" ::: "memory");
}

__global__ __launch_bounds__(GEMM_THREADS, 4) void gemm_kernel() {
    extern __shared__ __align__(128) char smem[];
    const uint32_t sm_base = smem_to_u32(smem);
    const int tid = threadIdx.x;
    const int wid = tid >> 5;
    const int lid = tid & 31;

    // block swizzle: groups of 32 m-blocks sweep all 16 n-blocks (A stays in L2)
    const int bid   = blockIdx.x;
    const int group = bid >> 9;            // / (32*16)
    const int inner = bid & 511;
    const int n_blk = inner >> 5;
    const int m_blk = (group << 5) | (inner & 31);
    const int m0 = m_blk * BM;
    const int n0 = n_blk * BN;

    // warp layout: 2 (m) x 2 (n); warp tile 64m x 32n
    const int wm0 = (wid >> 1) * 64;
    const int wn0 = (wid & 1) * 32;

    float acc[4][4][4];
#pragma unroll
    for (int i = 0; i < 4; i++)
#pragma unroll
        for (int j = 0; j < 4; j++)
#pragma unroll
            for (int q = 0; q < 4; q++) acc[i][j][q] = 0.f;

    load_tile(sm_base, 0, 0, m0, n0, tid);
    load_tile(sm_base, 1, 1, m0, n0, tid);

    const int a_row_off = wm0 + (lid & 15);
    const int a_col_off = (lid >> 4) * 8;
    const int b_row_off = wn0 + ((lid & 16) >> 1) + (lid & 7);
    const int b_col_off = ((lid & 8) ? 8 : 0);

    for (int t = 0; t < NKTILES; t++) {
        const int st = t & 1;
        if (t + 1 < NKTILES) asm volatile("cp.async.wait_group 1;" ::: "memory");
        else                 asm volatile("cp.async.wait_group 0;" ::: "memory");
        __syncthreads();

        const uint32_t smA = sm_base + st * STAGE_BYTES;
        const uint32_t smB = smA + A_TILE_BYTES;

#pragma unroll
        for (int ks = 0; ks < 4; ks++) {
            const int col = ks * 16;
            uint32_t a[4][4], b[4][2];
#pragma unroll
            for (int i = 0; i < 4; i++)
                ldmatrix_x4(a[i], smA + (a_row_off + i * 16) * ROWB
                                      + (col + a_col_off) * 2);
#pragma unroll
            for (int j2 = 0; j2 < 2; j2++) {
                uint32_t r[4];
                ldmatrix_x4(r, smB + (b_row_off + j2 * 16) * ROWB
                                   + (col + b_col_off) * 2);
                b[j2 * 2 + 0][0] = r[0]; b[j2 * 2 + 0][1] = r[1];
                b[j2 * 2 + 1][0] = r[2]; b[j2 * 2 + 1][1] = r[3];
            }
#pragma unroll
            for (int i = 0; i < 4; i++)
#pragma unroll
                for (int j = 0; j < 4; j++)
                    mma_f16(acc[i][j], a[i], b[j]);
        }

        __syncthreads();
        if (t + 2 < NKTILES)
            load_tile(sm_base, st, t + 2, m0, n0, tid);
    }

    // epilogue: both halves -> fp16 (theta mirror / hdst)
    __half* outbase = (n0 < 512) ? g_theta16 : g_hdst16;
    const int nc0 = n0 & 511;
    const int er = lid >> 2;
    const int ec = (lid & 3) * 2;
#pragma unroll
    for (int i = 0; i < 4; i++) {
#pragma unroll
        for (int j = 0; j < 4; j++) {
            const int m = m0 + wm0 + i * 16 + er;
            const int n = nc0 + wn0 + j * 8 + ec;
            *reinterpret_cast<__half2*>(&outbase[(size_t)m * F + n]) =
                __float22half2_rn(make_float2(acc[i][j][0], acc[i][j][1]));
            *reinterpret_cast<__half2*>(&outbase[(size_t)(m + 8) * F + n]) =
                __float22half2_rn(make_float2(acc[i][j][2], acc[i][j][3]));
        }
    }
}

// ---------------- gather + max + add -------------------------------------------
// 2 nodes per 128-thread block; 64 lanes/node, 16B (8-half) gathered loads.
// out[n][c] = max_j theta16[src[n][j]][c] + hdst16[n][c]
__global__ __launch_bounds__(128) void gather_max_kernel(
    const void* __restrict__ src, float* __restrict__ out)
{
    const int grp  = threadIdx.x >> 6;               // 0..1 : node within block
    const int lane = threadIdx.x & 63;               // 0..63: uint4 lane
    const int n    = blockIdx.x * 2 + grp;

    __shared__ unsigned int sidx[2][KNN];
    if (lane < KNN) {
        if (g_idx_is64) {
            sidx[grp][lane] = (unsigned int)((const unsigned long long*)src)
                                  [(size_t)n * KNN + lane] & 0xFFFFu;
        } else {
            sidx[grp][lane] = ((const unsigned int*)src)
                                  [(size_t)n * KNN + lane] & 0xFFFFu;
        }
    }
    __syncthreads();

    const uint4* __restrict__ t16 = reinterpret_cast<const uint4*>(g_theta16);

    uint4 raw = t16[(size_t)sidx[grp][0] * (F / 8) + lane];
    __half2 m0 = *reinterpret_cast<__half2*>(&raw.x);
    __half2 m1 = *reinterpret_cast<__half2*>(&raw.y);
    __half2 m2 = *reinterpret_cast<__half2*>(&raw.z);
    __half2 m3 = *reinterpret_cast<__half2*>(&raw.w);
#pragma unroll
    for (int j = 1; j < KNN; j++) {
        uint4 r = t16[(size_t)sidx[grp][j] * (F / 8) + lane];
        m0 = __hmax2(m0, *reinterpret_cast<__half2*>(&r.x));
        m1 = __hmax2(m1, *reinterpret_cast<__half2*>(&r.y));
        m2 = __hmax2(m2, *reinterpret_cast<__half2*>(&r.z));
        m3 = __hmax2(m3, *reinterpret_cast<__half2*>(&r.w));
    }

    const uint4 hdraw =
        reinterpret_cast<const uint4*>(g_hdst16)[(size_t)n * (F / 8) + lane];
    const float2 hd0 = __half22float2(*reinterpret_cast<const __half2*>(&hdraw.x));
    const float2 hd1 = __half22float2(*reinterpret_cast<const __half2*>(&hdraw.y));
    const float2 hd2 = __half22float2(*reinterpret_cast<const __half2*>(&hdraw.z));
    const float2 hd3 = __half22float2(*reinterpret_cast<const __half2*>(&hdraw.w));

    const float2 f0 = __half22float2(m0);
    const float2 f1 = __half22float2(m1);
    const float2 f2 = __half22float2(m2);
    const float2 f3 = __half22float2(m3);

    float4 r0, r1;
    r0.x = f0.x + hd0.x; r0.y = f0.y + hd0.y;
    r0.z = f1.x + hd1.x; r0.w = f1.y + hd1.y;
    r1.x = f2.x + hd2.x; r1.y = f2.y + hd2.y;
    r1.z = f3.x + hd3.x; r1.w = f3.y + hd3.y;

    float4* dst = reinterpret_cast<float4*>(out) + (size_t)n * (F / 4) + lane * 2;
    dst[0] = r0;
    dst[1] = r1;
}

// ---------------------------------------------------------------------------------
extern "C" void kernel_launch(void* const* d_in, const int* in_sizes, int n_in,
                              void* d_out, int out_size)
{
    const void*  src  = nullptr;
    const float* feat = nullptr;
    const float* Wt   = nullptr;
    const float* Wp   = nullptr;

    for (int i = 0; i < n_in; i++) {
        const int s = in_sizes[i];
        if (s == NN * KNN)      src  = d_in[i];
        else if (s == NN * F)   feat = (const float*)d_in[i];
        else if (s == F * F) {
            if (!Wt) Wt = (const float*)d_in[i];
            else     Wp = (const float*)d_in[i];
        }
    }

    cudaFuncSetAttribute(gemm_kernel,
                         cudaFuncAttributeMaxDynamicSharedMemorySize, SM_TOTAL);

    prep_kernel<<<PREP_BLOCKS, 256>>>(feat, Wt, Wp, (const unsigned int*)src);
    gemm_kernel<<<(NN / BM) * (NOUT / BN), GEMM_THREADS, SM_TOTAL>>>();
    gather_max_kernel<<<NN / 2, 128>>>(src, (float*)d_out);
}